// round 7
// baseline (speedup 1.0000x reference)
#include <cuda_runtime.h>
#include <cuda_bf16.h>
#include <cstdint>

#define N_   8192
#define YD_  512
#define XD_  64
#define K_   16
#define S_   10
#define NS_  (N_*S_)
#define LOG2PI 1.8378770664093453

// ---- scratch (device globals) ----
__device__ float g_enc_mu[N_*XD_];
__device__ float g_enc_sig[N_*XD_];
__device__ __nv_bfloat16 g_xh[NS_*XD_];
__device__ __nv_bfloat16 g_web[YD_*128];   // [We_mu | We_sig] bf16, [k][128]
__device__ __nv_bfloat16 g_wmh[XD_*YD_];   // Wd_mu bf16
__device__ __nv_bfloat16 g_wsh[XD_*YD_];   // Wd_sig bf16
__device__ double g_acc[4];
__device__ int g_cnt = 0;

__device__ __forceinline__ float softplus_f(float v) {
    return fmaxf(v, 0.0f) + log1pf(__expf(-fabsf(v)));
}
__device__ __forceinline__ float softplus_fast(float v) {
    return fmaxf(v, 0.0f) + __logf(1.0f + __expf(-fabsf(v)));
}
__device__ __forceinline__ void ldsm_x4(uint32_t* r, uint32_t addr) {
    asm volatile("ldmatrix.sync.aligned.m8n8.x4.shared.b16 {%0,%1,%2,%3}, [%4];"
        : "=r"(r[0]), "=r"(r[1]), "=r"(r[2]), "=r"(r[3]) : "r"(addr));
}
__device__ __forceinline__ void ldsm_x4_t(uint32_t* r, uint32_t addr) {
    asm volatile("ldmatrix.sync.aligned.m8n8.x4.trans.shared.b16 {%0,%1,%2,%3}, [%4];"
        : "=r"(r[0]), "=r"(r[1]), "=r"(r[2]), "=r"(r[3]) : "r"(addr));
}
#define MMA_BF16(C, A, B0, B1)                                          \
    asm volatile(                                                       \
        "mma.sync.aligned.m16n8k16.row.col.f32.bf16.bf16.f32 "          \
        "{%0,%1,%2,%3}, {%4,%5,%6,%7}, {%8,%9}, {%0,%1,%2,%3};"         \
        : "+f"(C[0]), "+f"(C[1]), "+f"(C[2]), "+f"(C[3])                \
        : "r"(A[0]), "r"(A[1]), "r"(A[2]), "r"(A[3]), "r"(B0), "r"(B1))

// ============================================================
// Kernel 0: prep — convert all weights to bf16, zero g_acc.
// ============================================================
__global__ void __launch_bounds__(256) prep_kernel(
    const float* __restrict__ We_mu, const float* __restrict__ We_sig,
    const float* __restrict__ Wd_mu, const float* __restrict__ Wd_sig)
{
    int t = blockIdx.x * 256 + threadIdx.x;
    if (t < 4) g_acc[t] = 0.0;
    #pragma unroll
    for (int j = 0; j < 4; j++) {
        int idx = t + j * 8192;            // float4 index 0..32767
        if (idx < 8192) {                   // We_mu [512,64]
            int k = idx >> 4, c = (idx & 15) * 4;
            float4 v = *(const float4*)(We_mu + k * XD_ + c);
            *(__nv_bfloat162*)(g_web + k * 128 + c)     = __floats2bfloat162_rn(v.x, v.y);
            *(__nv_bfloat162*)(g_web + k * 128 + c + 2) = __floats2bfloat162_rn(v.z, v.w);
        } else if (idx < 16384) {           // We_sig
            int i = idx - 8192;
            int k = i >> 4, c = (i & 15) * 4;
            float4 v = *(const float4*)(We_sig + k * XD_ + c);
            *(__nv_bfloat162*)(g_web + k * 128 + 64 + c)     = __floats2bfloat162_rn(v.x, v.y);
            *(__nv_bfloat162*)(g_web + k * 128 + 64 + c + 2) = __floats2bfloat162_rn(v.z, v.w);
        } else if (idx < 24576) {           // Wd_mu linear
            int i = idx - 16384;
            float4 v = *(const float4*)(Wd_mu + i * 4);
            *(__nv_bfloat162*)(g_wmh + i * 4)     = __floats2bfloat162_rn(v.x, v.y);
            *(__nv_bfloat162*)(g_wmh + i * 4 + 2) = __floats2bfloat162_rn(v.z, v.w);
        } else {                            // Wd_sig linear
            int i = idx - 24576;
            float4 v = *(const float4*)(Wd_sig + i * 4);
            *(__nv_bfloat162*)(g_wsh + i * 4)     = __floats2bfloat162_rn(v.x, v.y);
            *(__nv_bfloat162*)(g_wsh + i * 4 + 2) = __floats2bfloat162_rn(v.z, v.w);
        }
    }
}

// ============================================================
// Kernel 1: bf16 encoder GEMM, BM=32, register double-buffering.
// grid 256, 8 warps (2M x 4N), warp tile 16x32.
// A tile: 32 rows x 64 k = 512 float4 (2/thread).
// B tile: 64 k-rows x 128 cols = 1024 uint4 (4/thread).
// ============================================================
#define ESA 72
#define ESB 136

__global__ void __launch_bounds__(256) encoder_kernel(
    const float* __restrict__ Y,
    const float* __restrict__ be_mu, const float* __restrict__ be_sig)
{
    __shared__ __align__(16) __nv_bfloat16 sA[32 * ESA];
    __shared__ __align__(16) __nv_bfloat16 sB[64 * ESB];

    int tid = threadIdx.x;
    int warp = tid >> 5, lane = tid & 31;
    int row0 = blockIdx.x * 32;

    // A staging: float4 indices tid and tid+256; 16 float4 per 64-col row
    int ar  = tid >> 4,        ac4  = (tid & 15) * 4;
    int ar2 = ar + 16,         ac42 = ac4;            // (tid+256)>>4 = ar+16
    float4 rA[2];
    uint4  rB[4];

    #define ENC_LOAD(kc)                                                      \
    {   int k0 = (kc) * 64;                                                   \
        rA[0] = *(const float4*)(Y + (size_t)(row0 + ar) * YD_ + k0 + ac4);   \
        rA[1] = *(const float4*)(Y + (size_t)(row0 + ar2) * YD_ + k0 + ac42); \
        _Pragma("unroll")                                                     \
        for (int j = 0; j < 4; j++) {                                         \
            int i = tid + j * 256;                                            \
            rB[j] = *(const uint4*)(g_web + (size_t)(k0 + (i >> 4)) * 128 + (i & 15) * 8); \
        }                                                                     \
    }
    #define ENC_STORE()                                                      \
    {   *(__nv_bfloat162*)(sA + ar * ESA + ac4)       = __floats2bfloat162_rn(rA[0].x, rA[0].y); \
        *(__nv_bfloat162*)(sA + ar * ESA + ac4 + 2)   = __floats2bfloat162_rn(rA[0].z, rA[0].w); \
        *(__nv_bfloat162*)(sA + ar2 * ESA + ac42)     = __floats2bfloat162_rn(rA[1].x, rA[1].y); \
        *(__nv_bfloat162*)(sA + ar2 * ESA + ac42 + 2) = __floats2bfloat162_rn(rA[1].z, rA[1].w); \
        _Pragma("unroll")                                                     \
        for (int j = 0; j < 4; j++) {                                         \
            int i = tid + j * 256;                                            \
            *(uint4*)(sB + (i >> 4) * ESB + (i & 15) * 8) = rB[j];            \
        }                                                                     \
    }

    int mBase = (warp & 1) * 16;
    int nBase = (warp >> 1) * 32;
    int g = lane >> 2, tg = lane & 3;
    int mi = lane >> 3, ri = lane & 7;

    uint32_t aBase = (uint32_t)__cvta_generic_to_shared(sA);
    uint32_t bBase = (uint32_t)__cvta_generic_to_shared(sB);
    uint32_t aAddr = aBase +
        (((mBase + (mi & 1) * 8 + ri) * ESA) + (mi >> 1) * 8) * 2;
    uint32_t bAddr[2];
    #pragma unroll
    for (int p = 0; p < 2; p++)
        bAddr[p] = bBase +
            ((((mi & 1) * 8 + ri) * ESB) + nBase + p * 16 + (mi >> 1) * 8) * 2;

    float acc[4][4];
    #pragma unroll
    for (int nt = 0; nt < 4; nt++)
        #pragma unroll
        for (int r = 0; r < 4; r++) acc[nt][r] = 0.f;

    ENC_LOAD(0);
    for (int kc = 0; kc < 8; kc++) {
        ENC_STORE();
        __syncthreads();
        if (kc < 7) ENC_LOAD(kc + 1);   // prefetch overlaps MMAs
        #pragma unroll
        for (int ks = 0; ks < 4; ks++) {
            uint32_t a[4];
            ldsm_x4(a, aAddr + ks * 32);
            uint32_t b[2][4];
            ldsm_x4_t(b[0], bAddr[0] + ks * (16 * ESB * 2));
            ldsm_x4_t(b[1], bAddr[1] + ks * (16 * ESB * 2));
            #pragma unroll
            for (int nt = 0; nt < 4; nt++) {
                int p = nt >> 1, sel = (nt & 1) * 2;
                MMA_BF16(acc[nt], a, b[p][sel], b[p][sel + 1]);
            }
        }
        __syncthreads();
    }

    #pragma unroll
    for (int half = 0; half < 2; half++) {
        int row = row0 + mBase + g + half * 8;
        #pragma unroll
        for (int nt = 0; nt < 4; nt++) {
            #pragma unroll
            for (int p = 0; p < 2; p++) {
                int cl = nBase + nt * 8 + tg * 2 + p;
                float c = acc[nt][half * 2 + p];
                if (cl < 64) {
                    g_enc_mu[row * XD_ + cl] = c + be_mu[cl];
                } else {
                    int cc = cl - 64;
                    g_enc_sig[row * XD_ + cc] = softplus_f(c + be_sig[cc]) + 1e-3f;
                }
            }
        }
    }
}

// ============================================================
// Kernel 2: fused GMM responsibilities + gumbel-softmax mixtures.
// Two n per 128-thread block; s-loop split in halves of 5.
// ============================================================
__global__ void __launch_bounds__(128) mixture_kernel(
    const float* __restrict__ phi_mus, const float* __restrict__ phi_sigs,
    const float* __restrict__ phi_logits,
    const float* __restrict__ theta_mus, const float* __restrict__ theta_sigs,
    const float* __restrict__ theta_logits,
    const float* __restrict__ u_noise, const float* __restrict__ eps_noise,
    const float* __restrict__ temperature)
{
    int tid = threadIdx.x;
    int sub = tid >> 6;
    int d = tid & 63;
    int n = blockIdx.x * 2 + sub;

    __shared__ float s_pmu[16 * 65], s_psg[16 * 65];
    __shared__ float s_tmu[16 * 65], s_tsg[16 * 65];
    __shared__ float s_mut[2][16 * 65], s_sgt[2][16 * 65];
    __shared__ float em[2][64], es[2][64];
    __shared__ float lpi[16], lth[16];
    __shared__ float zl[2][16], zlp[2][16];
    __shared__ float s_z[2][S_][17];
    __shared__ float sdt[2][S_];
    __shared__ float red[2][16][4];
    __shared__ float wred[2][2];
    __shared__ float sl5[2];

    for (int k = sub; k < 16; k += 2) {
        s_pmu[k * 65 + d] = phi_mus[k * XD_ + d];
        s_psg[k * 65 + d] = phi_sigs[k * XD_ + d];
        s_tmu[k * 65 + d] = theta_mus[k * XD_ + d];
        s_tsg[k * 65 + d] = theta_sigs[k * XD_ + d];
    }
    float emd = g_enc_mu[n * XD_ + d];
    float esd = g_enc_sig[n * XD_ + d];
    em[sub][d] = emd; es[sub][d] = esd;
    float iesd = 1.0f / esd;

    if (tid == 0) {
        float m = -1e30f;
        for (int k = 0; k < 16; k++) m = fmaxf(m, phi_logits[k]);
        float sm = 0.0f;
        for (int k = 0; k < 16; k++) sm += __expf(phi_logits[k] - m);
        float lse = m + __logf(sm);
        for (int k = 0; k < 16; k++) lpi[k] = phi_logits[k] - lse;
    }
    if (tid == 1) {
        float m = -1e30f;
        for (int k = 0; k < 16; k++) m = fmaxf(m, theta_logits[k]);
        float sm = 0.0f;
        for (int k = 0; k < 16; k++) sm += __expf(theta_logits[k] - m);
        float lse = m + __logf(sm);
        for (int k = 0; k < 16; k++) lth[k] = theta_logits[k] - lse;
    }
    __syncthreads();

    // posterior tables (thread-private columns: no sync needed before use)
    #pragma unroll
    for (int k = 0; k < 16; k++) {
        float psig = s_psg[k * 65 + d];
        float ig = __fdividef(1.0f, psig);
        float st = __fdividef(1.0f, iesd + ig);
        s_sgt[sub][k * 65 + d] = st;
        s_mut[sub][k * 65 + d] = st * fmaf(ig, s_pmu[k * 65 + d], iesd * emd);
    }

    {
        int k = d >> 2, g4 = d & 3;
        float a = 0.0f, prod = 1.0f;
        #pragma unroll
        for (int i = 0; i < 16; i++) {
            int dd = g4 * 16 + i;
            float std = es[sub][dd] + s_psg[k * 65 + dd];
            float t = __fdividef(em[sub][dd] - s_pmu[k * 65 + dd], std);
            a += 0.5f * t * t;
            prod *= std;
        }
        red[sub][k][g4] = a + __logf(prod);
    }
    __syncthreads();
    if (d < 16)
        zl[sub][d] = lpi[d] - 0.5f * 64.0f * (float)LOG2PI
            - (red[sub][d][0] + red[sub][d][1] + red[sub][d][2] + red[sub][d][3]);
    __syncthreads();
    if (d == 0) {
        float m = -1e30f;
        for (int k = 0; k < 16; k++) m = fmaxf(m, zl[sub][k]);
        float sm = 0.0f;
        for (int k = 0; k < 16; k++) sm += __expf(zl[sub][k] - m);
        float lse = m + __logf(sm);
        for (int k = 0; k < 16; k++) zlp[sub][k] = zl[sub][k] - lse;
        float s2 = 0.0f;
        for (int k = 0; k < 16; k++) s2 += __expf(zlp[sub][k]);
        sl5[sub] = __logf(s2);
    }
    __syncthreads();

    float invT = 1.0f / temperature[0];
    if (d < S_) {
        int s = d;
        const float* urow = u_noise + (size_t)n * (S_ * K_) + s * K_;
        float v[16];
        float m = -1e30f;
        #pragma unroll
        for (int k = 0; k < 16; k++) {
            float gg = -__logf(-__logf(urow[k]));
            v[k] = (zlp[sub][k] + gg) * invT;
            m = fmaxf(m, v[k]);
        }
        float sm = 0.0f;
        #pragma unroll
        for (int k = 0; k < 16; k++) { v[k] = __expf(v[k] - m); sm += v[k]; }
        float inv = 1.0f / sm;
        float dt = 0.0f;
        #pragma unroll
        for (int k = 0; k < 16; k++) {
            float z = v[k] * inv;
            s_z[sub][s][k] = z;
            dt = fmaf(z, lth[k] - zlp[sub][k], dt);
        }
        sdt[sub][s] = dt;
    }
    __syncthreads();

    float lacc = 0.0f, lp = 1.0f;
    #pragma unroll
    for (int h = 0; h < 2; h++) {
        float ms[5], ssg[5], tm[5], tsg[5], pm[5], psg[5];
        #pragma unroll
        for (int j = 0; j < 5; j++) {
            ms[j] = 0.f; ssg[j] = 0.f; tm[j] = 0.f;
            tsg[j] = 0.f; pm[j] = 0.f; psg[j] = 0.f;
        }
        #pragma unroll
        for (int k = 0; k < 16; k++) {
            float mut  = s_mut[sub][k * 65 + d];
            float sgt  = s_sgt[sub][k * 65 + d];
            float tmu  = s_tmu[k * 65 + d];
            float tsig = s_tsg[k * 65 + d];
            float pmu  = s_pmu[k * 65 + d];
            float psig = s_psg[k * 65 + d];
            #pragma unroll
            for (int j = 0; j < 5; j++) {
                float z = s_z[sub][h * 5 + j][k];
                ms[j]  = fmaf(z, mut, ms[j]);
                ssg[j] = fmaf(z, sgt, ssg[j]);
                tm[j]  = fmaf(z, tmu, tm[j]);
                tsg[j] = fmaf(z, tsig, tsg[j]);
                pm[j]  = fmaf(z, pmu, pm[j]);
                psg[j] = fmaf(z, psig, psg[j]);
            }
        }
        #pragma unroll
        for (int j = 0; j < 5; j++) {
            int s = h * 5 + j;
            int row = n * S_ + s;
            float x = fmaf(sqrtf(ssg[j]), eps_noise[(size_t)row * XD_ + d], ms[j]);
            g_xh[(size_t)row * XD_ + d] = __float2bfloat16_rn(x);
            float te = (x - emd) * iesd;
            float rt = __fdividef(1.0f, tsg[j]);
            float rp = __fdividef(1.0f, psg[j]);
            float tt = (x - tm[j]) * rt;
            float tp = (x - pm[j]) * rp;
            lacc += 0.5f * (te * te - tt * tt + tp * tp);
            lp *= psg[j] * rt;
        }
    }
    lacc += __logf(lp) + (float)S_ * __logf(esd);

    #pragma unroll
    for (int o = 16; o > 0; o >>= 1)
        lacc += __shfl_down_sync(0xffffffffu, lacc, o);
    if ((tid & 31) == 0) wred[sub][(tid >> 5) & 1] = lacc;
    __syncthreads();
    if (d == 0) {
        float dts = 0.0f;
        #pragma unroll
        for (int s = 0; s < S_; s++) dts += sdt[sub][s];
        double tot = (double)(wred[sub][0] + wred[sub][1]) + (double)dts;
        atomicAdd(&g_acc[1], tot);
        atomicAdd(&g_acc[2], (double)sl5[sub]);
    }
}

// ============================================================
// Kernel 3: bf16 decoder GEMMs fused with loss1 + final combine.
// ============================================================
#define SA 72
#define SB 72
#define DEC_GRID ((NS_/64)*(YD_/64))

__global__ void __launch_bounds__(256, 3) decoder_kernel(
    const float* __restrict__ Y, const float* __restrict__ bd_mu,
    const float* __restrict__ bd_sig, float* __restrict__ out)
{
    __shared__ __align__(16) __nv_bfloat16 sA[64 * SA];
    __shared__ __align__(16) __nv_bfloat16 sBm[64 * SB];
    __shared__ __align__(16) __nv_bfloat16 sBs[64 * SB];
    __shared__ float sY[8][68];
    __shared__ float sbm[64], sbs[64];
    __shared__ float warp_red[8];

    int tid = threadIdx.x;
    int warp = tid >> 5, lane = tid & 31;
    int row0 = blockIdx.x * 64;
    int col0 = blockIdx.y * 64;
    int n0 = row0 / S_;

    const __nv_bfloat16* gx = g_xh + (size_t)row0 * XD_;
    #pragma unroll
    for (int i = tid; i < 64 * 8; i += 256) {
        int r = i >> 3, c8 = (i & 7) * 8;
        *(uint4*)(sA + r * SA + c8) = *(const uint4*)(gx + r * XD_ + c8);
    }
    #pragma unroll
    for (int i = tid; i < 64 * 8; i += 256) {
        int k = i >> 3, c8 = (i & 7) * 8;
        *(uint4*)(sBm + k * SB + c8) = *(const uint4*)(g_wmh + k * YD_ + col0 + c8);
        *(uint4*)(sBs + k * SB + c8) = *(const uint4*)(g_wsh + k * YD_ + col0 + c8);
    }
    if (tid < 128) {
        int r = tid >> 4, c4 = (tid & 15) * 4;
        int nr = min(n0 + r, N_ - 1);
        float4 v = *(const float4*)(Y + (size_t)nr * YD_ + col0 + c4);
        sY[r][c4] = v.x; sY[r][c4 + 1] = v.y;
        sY[r][c4 + 2] = v.z; sY[r][c4 + 3] = v.w;
    } else if (tid < 192) {
        int t = tid - 128;
        sbm[t] = bd_mu[col0 + t];
        sbs[t] = bd_sig[col0 + t];
    }
    __syncthreads();

    int mBase = (warp & 3) * 16;
    int nBase = (warp >> 2) * 32;
    int g = lane >> 2, tg = lane & 3;
    int mi = lane >> 3, ri = lane & 7;

    uint32_t aBase  = (uint32_t)__cvta_generic_to_shared(sA);
    uint32_t bmBase = (uint32_t)__cvta_generic_to_shared(sBm);
    uint32_t bsBase = (uint32_t)__cvta_generic_to_shared(sBs);
    uint32_t aAddr = aBase +
        (((mBase + (mi & 1) * 8 + ri) * SA) + (mi >> 1) * 8) * 2;
    uint32_t bmAddr[2], bsAddr[2];
    #pragma unroll
    for (int p = 0; p < 2; p++) {
        uint32_t off = (((mi & 1) * 8 + ri) * SB + nBase + p * 16 + (mi >> 1) * 8) * 2;
        bmAddr[p] = bmBase + off;
        bsAddr[p] = bsBase + off;
    }

    float cm[4][4], cs[4][4];
    #pragma unroll
    for (int nt = 0; nt < 4; nt++)
        #pragma unroll
        for (int r = 0; r < 4; r++) { cm[nt][r] = 0.f; cs[nt][r] = 0.f; }

    #pragma unroll
    for (int ks = 0; ks < 4; ks++) {
        uint32_t a[4];
        ldsm_x4(a, aAddr + ks * 32);
        uint32_t bm[2][4], bs[2][4];
        #pragma unroll
        for (int p = 0; p < 2; p++) {
            ldsm_x4_t(bm[p], bmAddr[p] + ks * (16 * SB * 2));
            ldsm_x4_t(bs[p], bsAddr[p] + ks * (16 * SB * 2));
        }
        #pragma unroll
        for (int nt = 0; nt < 4; nt++) {
            int p = nt >> 1, sel = (nt & 1) * 2;
            MMA_BF16(cm[nt], a, bm[p][sel], bm[p][sel + 1]);
            MMA_BF16(cs[nt], a, bs[p][sel], bs[p][sel + 1]);
        }
    }

    float part = 0.0f;
    #pragma unroll
    for (int half = 0; half < 2; half++) {
        int row = row0 + mBase + g + half * 8;
        int yr = row / S_ - n0;
        float prod = 1.0f;
        #pragma unroll
        for (int nt = 0; nt < 4; nt++) {
            #pragma unroll
            for (int p = 0; p < 2; p++) {
                int r = half * 2 + p;
                int cl = nBase + nt * 8 + tg * 2 + p;
                float mu = cm[nt][r] + sbm[cl];
                float sg = softplus_fast(cs[nt][r] + sbs[cl]) + 1e-3f;
                float t = __fdividef(sY[yr][cl] - mu, sg);
                part -= 0.5f * t * t;
                prod *= sg;
            }
        }
        part -= __logf(prod);
    }
    #pragma unroll
    for (int o = 16; o > 0; o >>= 1)
        part += __shfl_down_sync(0xffffffffu, part, o);
    if (lane == 0) warp_red[warp] = part;
    __syncthreads();
    if (tid == 0) {
        float tot = 0.0f;
        #pragma unroll
        for (int w = 0; w < 8; w++) tot += warp_red[w];
        atomicAdd(&g_acc[0], (double)tot);
        __threadfence();
        int ticket = atomicAdd(&g_cnt, 1);
        if (ticket == DEC_GRID - 1) {
            g_cnt = 0;
            double NSd = (double)NS_;
            double L1   = g_acc[0] - 0.5 * (double)YD_ * LOG2PI * NSd;
            double L234 = g_acc[1] + 0.5 * (double)XD_ * LOG2PI * NSd;
            double totl = (L1 + L234) / (double)S_ + g_acc[2];
            out[0] = (float)(-totl);
        }
    }
}

extern "C" void kernel_launch(void* const* d_in, const int* in_sizes, int n_in,
                              void* d_out, int out_size)
{
    const float* Y            = (const float*)d_in[0];
    const float* We_mu        = (const float*)d_in[1];
    const float* be_mu        = (const float*)d_in[2];
    const float* We_sig       = (const float*)d_in[3];
    const float* be_sig       = (const float*)d_in[4];
    const float* Wd_mu        = (const float*)d_in[5];
    const float* bd_mu        = (const float*)d_in[6];
    const float* Wd_sig       = (const float*)d_in[7];
    const float* bd_sig       = (const float*)d_in[8];
    const float* phi_mus      = (const float*)d_in[9];
    const float* phi_sigs     = (const float*)d_in[10];
    const float* phi_logits   = (const float*)d_in[11];
    const float* theta_mus    = (const float*)d_in[12];
    const float* theta_sigs   = (const float*)d_in[13];
    const float* theta_logits = (const float*)d_in[14];
    const float* u_noise      = (const float*)d_in[15];
    const float* eps_noise    = (const float*)d_in[16];
    const float* temperature  = (const float*)d_in[17];

    prep_kernel<<<32, 256>>>(We_mu, We_sig, Wd_mu, Wd_sig);
    encoder_kernel<<<N_ / 32, 256>>>(Y, be_mu, be_sig);
    mixture_kernel<<<N_ / 2, 128>>>(phi_mus, phi_sigs, phi_logits,
                                    theta_mus, theta_sigs, theta_logits,
                                    u_noise, eps_noise, temperature);
    decoder_kernel<<<dim3(NS_ / 64, YD_ / 64), 256>>>(Y, bd_mu, bd_sig,
                                                      (float*)d_out);
}

// round 8
// speedup vs baseline: 1.1241x; 1.1241x over previous
#include <cuda_runtime.h>
#include <cuda_bf16.h>
#include <cstdint>

#define N_   8192
#define YD_  512
#define XD_  64
#define K_   16
#define S_   10
#define NS_  (N_*S_)
#define LOG2PI 1.8378770664093453

// ---- scratch (device globals) ----
__device__ float g_enc_mu[N_*XD_];
__device__ float g_enc_sig[N_*XD_];
__device__ __nv_bfloat16 g_xh[NS_*XD_];
__device__ double g_acc[4];   // 0: loss1, 1: loss2+3+4, 2: loss5
__device__ int g_cnt = 0;

__device__ __forceinline__ float softplus_f(float v) {
    return fmaxf(v, 0.0f) + log1pf(__expf(-fabsf(v)));
}
__device__ __forceinline__ float softplus_fast(float v) {
    return fmaxf(v, 0.0f) + __logf(1.0f + __expf(-fabsf(v)));
}
__device__ __forceinline__ void ldsm_x4(uint32_t* r, uint32_t addr) {
    asm volatile("ldmatrix.sync.aligned.m8n8.x4.shared.b16 {%0,%1,%2,%3}, [%4];"
        : "=r"(r[0]), "=r"(r[1]), "=r"(r[2]), "=r"(r[3]) : "r"(addr));
}
__device__ __forceinline__ void ldsm_x4_t(uint32_t* r, uint32_t addr) {
    asm volatile("ldmatrix.sync.aligned.m8n8.x4.trans.shared.b16 {%0,%1,%2,%3}, [%4];"
        : "=r"(r[0]), "=r"(r[1]), "=r"(r[2]), "=r"(r[3]) : "r"(addr));
}
#define MMA_BF16(C, A, B0, B1)                                          \
    asm volatile(                                                       \
        "mma.sync.aligned.m16n8k16.row.col.f32.bf16.bf16.f32 "          \
        "{%0,%1,%2,%3}, {%4,%5,%6,%7}, {%8,%9}, {%0,%1,%2,%3};"         \
        : "+f"(C[0]), "+f"(C[1]), "+f"(C[2]), "+f"(C[3])                \
        : "r"(A[0]), "r"(A[1]), "r"(A[2]), "r"(A[3]), "r"(B0), "r"(B1))

// ============================================================
// Kernel 1: bf16 tensor-core encoder GEMM (R4 exact).
// C[8192,128] = Y[8192,512] @ [We_mu | We_sig].
// BM=64, BN=128, 256 thr, 8 warps (2M x 4N), warp tile 32x32.
// Also zeroes g_acc (block 0).
// ============================================================
#define ESA 72
#define ESB 136

__global__ void __launch_bounds__(256) encoder_kernel(
    const float* __restrict__ Y,
    const float* __restrict__ We_mu, const float* __restrict__ be_mu,
    const float* __restrict__ We_sig, const float* __restrict__ be_sig)
{
    __shared__ __align__(16) __nv_bfloat16 sA[64 * ESA];
    __shared__ __align__(16) __nv_bfloat16 sB[64 * ESB];

    int tid = threadIdx.x;
    int warp = tid >> 5, lane = tid & 31;
    int row0 = blockIdx.x * 64;

    if (blockIdx.x == 0 && tid < 4) g_acc[tid] = 0.0;

    int mBase = (warp & 1) * 32;
    int nBase = (warp >> 1) * 32;
    int g = lane >> 2, tg = lane & 3;
    int mi = lane >> 3, ri = lane & 7;

    uint32_t aBase = (uint32_t)__cvta_generic_to_shared(sA);
    uint32_t bBase = (uint32_t)__cvta_generic_to_shared(sB);
    uint32_t aAddr[2];
    #pragma unroll
    for (int mt = 0; mt < 2; mt++)
        aAddr[mt] = aBase +
            (((mBase + mt * 16 + (mi & 1) * 8 + ri) * ESA) + (mi >> 1) * 8) * 2;
    uint32_t bAddr[2];
    #pragma unroll
    for (int p = 0; p < 2; p++)
        bAddr[p] = bBase +
            ((((mi & 1) * 8 + ri) * ESB) + nBase + p * 16 + (mi >> 1) * 8) * 2;

    float acc[2][4][4];
    #pragma unroll
    for (int mt = 0; mt < 2; mt++)
        #pragma unroll
        for (int nt = 0; nt < 4; nt++)
            #pragma unroll
            for (int r = 0; r < 4; r++) acc[mt][nt][r] = 0.f;

    for (int kc = 0; kc < 8; kc++) {
        int k0 = kc * 64;
        #pragma unroll
        for (int i = tid; i < 64 * 16; i += 256) {
            int r = i >> 4, c4 = (i & 15) * 4;
            float4 v = *(const float4*)(Y + (size_t)(row0 + r) * YD_ + k0 + c4);
            *(__nv_bfloat162*)(sA + r * ESA + c4)     = __floats2bfloat162_rn(v.x, v.y);
            *(__nv_bfloat162*)(sA + r * ESA + c4 + 2) = __floats2bfloat162_rn(v.z, v.w);
        }
        #pragma unroll
        for (int i = tid; i < 64 * 32; i += 256) {
            int k = i >> 5, c4 = (i & 31) * 4;
            const float* src = (c4 < 64) ? We_mu + (k0 + k) * XD_ + c4
                                         : We_sig + (k0 + k) * XD_ + (c4 - 64);
            float4 v = *(const float4*)src;
            *(__nv_bfloat162*)(sB + k * ESB + c4)     = __floats2bfloat162_rn(v.x, v.y);
            *(__nv_bfloat162*)(sB + k * ESB + c4 + 2) = __floats2bfloat162_rn(v.z, v.w);
        }
        __syncthreads();
        #pragma unroll
        for (int ks = 0; ks < 4; ks++) {
            uint32_t a[2][4];
            ldsm_x4(a[0], aAddr[0] + ks * 32);
            ldsm_x4(a[1], aAddr[1] + ks * 32);
            uint32_t b[2][4];
            ldsm_x4_t(b[0], bAddr[0] + ks * (16 * ESB * 2));
            ldsm_x4_t(b[1], bAddr[1] + ks * (16 * ESB * 2));
            #pragma unroll
            for (int nt = 0; nt < 4; nt++) {
                int p = nt >> 1, sel = (nt & 1) * 2;
                MMA_BF16(acc[0][nt], a[0], b[p][sel], b[p][sel + 1]);
                MMA_BF16(acc[1][nt], a[1], b[p][sel], b[p][sel + 1]);
            }
        }
        __syncthreads();
    }
    #pragma unroll
    for (int mt = 0; mt < 2; mt++) {
        #pragma unroll
        for (int half = 0; half < 2; half++) {
            int row = row0 + mBase + mt * 16 + g + half * 8;
            #pragma unroll
            for (int nt = 0; nt < 4; nt++) {
                #pragma unroll
                for (int p = 0; p < 2; p++) {
                    int cl = nBase + nt * 8 + tg * 2 + p;
                    float c = acc[mt][nt][half * 2 + p];
                    if (cl < 64) {
                        g_enc_mu[row * XD_ + cl] = c + be_mu[cl];
                    } else {
                        int cc = cl - 64;
                        g_enc_sig[row * XD_ + cc] =
                            softplus_f(c + be_sig[cc]) + 1e-3f;
                    }
                }
            }
        }
    }
}

// ============================================================
// Kernel 2: fused GMM responsibilities + gumbel-softmax mixtures
// (R4 exact). Two n per 128-thread block.
// ============================================================
__global__ void __launch_bounds__(128) mixture_kernel(
    const float* __restrict__ phi_mus, const float* __restrict__ phi_sigs,
    const float* __restrict__ phi_logits,
    const float* __restrict__ theta_mus, const float* __restrict__ theta_sigs,
    const float* __restrict__ theta_logits,
    const float* __restrict__ u_noise, const float* __restrict__ eps_noise,
    const float* __restrict__ temperature)
{
    int tid = threadIdx.x;
    int sub = tid >> 6;
    int d = tid & 63;
    int n = blockIdx.x * 2 + sub;

    __shared__ float s_pmu[16 * 65], s_psg[16 * 65];
    __shared__ float s_tmu[16 * 65], s_tsg[16 * 65];
    __shared__ float em[2][64], es[2][64];
    __shared__ float lpi[16], lth[16];
    __shared__ float zl[2][16], zlp[2][16];
    __shared__ float s_z[2][S_][17];
    __shared__ float sdt[2][S_];
    __shared__ float red[2][16][4];
    __shared__ float wred[2][2];
    __shared__ float sl5[2];

    for (int k = sub; k < 16; k += 2) {
        s_pmu[k * 65 + d] = phi_mus[k * XD_ + d];
        s_psg[k * 65 + d] = phi_sigs[k * XD_ + d];
        s_tmu[k * 65 + d] = theta_mus[k * XD_ + d];
        s_tsg[k * 65 + d] = theta_sigs[k * XD_ + d];
    }
    float emd = g_enc_mu[n * XD_ + d];
    float esd = g_enc_sig[n * XD_ + d];
    em[sub][d] = emd; es[sub][d] = esd;
    float iesd = 1.0f / esd;

    if (tid == 0) {
        float m = -1e30f;
        for (int k = 0; k < 16; k++) m = fmaxf(m, phi_logits[k]);
        float sm = 0.0f;
        for (int k = 0; k < 16; k++) sm += __expf(phi_logits[k] - m);
        float lse = m + __logf(sm);
        for (int k = 0; k < 16; k++) lpi[k] = phi_logits[k] - lse;
    }
    if (tid == 1) {
        float m = -1e30f;
        for (int k = 0; k < 16; k++) m = fmaxf(m, theta_logits[k]);
        float sm = 0.0f;
        for (int k = 0; k < 16; k++) sm += __expf(theta_logits[k] - m);
        float lse = m + __logf(sm);
        for (int k = 0; k < 16; k++) lth[k] = theta_logits[k] - lse;
    }
    __syncthreads();

    {
        int k = d >> 2, g4 = d & 3;
        float a = 0.0f, prod = 1.0f;
        #pragma unroll
        for (int i = 0; i < 16; i++) {
            int dd = g4 * 16 + i;
            float std = es[sub][dd] + s_psg[k * 65 + dd];
            float t = __fdividef(em[sub][dd] - s_pmu[k * 65 + dd], std);
            a += 0.5f * t * t;
            prod *= std;
        }
        red[sub][k][g4] = a + __logf(prod);
    }
    __syncthreads();
    if (d < 16)
        zl[sub][d] = lpi[d] - 0.5f * 64.0f * (float)LOG2PI
            - (red[sub][d][0] + red[sub][d][1] + red[sub][d][2] + red[sub][d][3]);
    __syncthreads();
    if (d == 0) {
        float m = -1e30f;
        for (int k = 0; k < 16; k++) m = fmaxf(m, zl[sub][k]);
        float sm = 0.0f;
        for (int k = 0; k < 16; k++) sm += __expf(zl[sub][k] - m);
        float lse = m + __logf(sm);
        for (int k = 0; k < 16; k++) zlp[sub][k] = zl[sub][k] - lse;
        float s2 = 0.0f;
        for (int k = 0; k < 16; k++) s2 += __expf(zlp[sub][k]);
        sl5[sub] = __logf(s2);
    }
    __syncthreads();

    float invT = 1.0f / temperature[0];
    if (d < S_) {
        int s = d;
        const float* urow = u_noise + (size_t)n * (S_ * K_) + s * K_;
        float v[16];
        float m = -1e30f;
        #pragma unroll
        for (int k = 0; k < 16; k++) {
            float gg = -__logf(-__logf(urow[k]));
            v[k] = (zlp[sub][k] + gg) * invT;
            m = fmaxf(m, v[k]);
        }
        float sm = 0.0f;
        #pragma unroll
        for (int k = 0; k < 16; k++) { v[k] = __expf(v[k] - m); sm += v[k]; }
        float inv = 1.0f / sm;
        float dt = 0.0f;
        #pragma unroll
        for (int k = 0; k < 16; k++) {
            float z = v[k] * inv;
            s_z[sub][s][k] = z;
            dt = fmaf(z, lth[k] - zlp[sub][k], dt);
        }
        sdt[sub][s] = dt;
    }
    __syncthreads();

    float ms[S_], ssg[S_], tm[S_], tsg[S_], pm[S_], psg[S_];
    #pragma unroll
    for (int s = 0; s < S_; s++) {
        ms[s] = 0.f; ssg[s] = 0.f; tm[s] = 0.f;
        tsg[s] = 0.f; pm[s] = 0.f; psg[s] = 0.f;
    }
    #pragma unroll
    for (int k = 0; k < 16; k++) {
        float pmu  = s_pmu[k * 65 + d];
        float psig = s_psg[k * 65 + d];
        float tmu  = s_tmu[k * 65 + d];
        float tsig = s_tsg[k * 65 + d];
        float ig = __fdividef(1.0f, psig);
        float st = __fdividef(1.0f, iesd + ig);
        float mut = st * fmaf(ig, pmu, iesd * emd);
        #pragma unroll
        for (int s = 0; s < S_; s++) {
            float z = s_z[sub][s][k];
            ms[s]  = fmaf(z, mut, ms[s]);
            ssg[s] = fmaf(z, st, ssg[s]);
            tm[s]  = fmaf(z, tmu, tm[s]);
            tsg[s] = fmaf(z, tsig, tsg[s]);
            pm[s]  = fmaf(z, pmu, pm[s]);
            psg[s] = fmaf(z, psig, psg[s]);
        }
    }

    float lacc = 0.0f;
    float lp = 1.0f;
    #pragma unroll
    for (int s = 0; s < S_; s++) {
        int row = n * S_ + s;
        float x = fmaf(sqrtf(ssg[s]), eps_noise[(size_t)row * XD_ + d], ms[s]);
        g_xh[(size_t)row * XD_ + d] = __float2bfloat16_rn(x);
        float te = (x - emd) * iesd;
        float rt = __fdividef(1.0f, tsg[s]);
        float rp = __fdividef(1.0f, psg[s]);
        float tt = (x - tm[s]) * rt;
        float tp = (x - pm[s]) * rp;
        lacc += 0.5f * (te * te - tt * tt + tp * tp);
        lp *= psg[s] * rt;
    }
    lacc += __logf(lp) + (float)S_ * __logf(esd);

    #pragma unroll
    for (int o = 16; o > 0; o >>= 1)
        lacc += __shfl_down_sync(0xffffffffu, lacc, o);
    if ((tid & 31) == 0) wred[sub][(tid >> 5) & 1] = lacc;
    __syncthreads();
    if (d == 0) {
        float dts = 0.0f;
        #pragma unroll
        for (int s = 0; s < S_; s++) dts += sdt[sub][s];
        double tot = (double)(wred[sub][0] + wred[sub][1]) + (double)dts;
        atomicAdd(&g_acc[1], tot);
        atomicAdd(&g_acc[2], (double)sl5[sub]);
    }
}

// ============================================================
// Kernel 3: bf16 decoder GEMMs fused with loss1 (R3 exact tile:
// BM=128, BN=64, 8 warps 4Mx2N, warp tile 32x32, inline weight
// conversion, direct-Y epilogue) + fused finalize ticket.
// ============================================================
#define SA 72
#define SB 72
#define DBM 128
#define DEC_GRID ((NS_/DBM)*(YD_/64))

__global__ void __launch_bounds__(256) decoder_kernel(
    const float* __restrict__ Y,
    const float* __restrict__ Wd_mu, const float* __restrict__ bd_mu,
    const float* __restrict__ Wd_sig, const float* __restrict__ bd_sig,
    float* __restrict__ out)
{
    __shared__ __align__(16) __nv_bfloat16 sA[DBM * SA];
    __shared__ __align__(16) __nv_bfloat16 sBm[64 * SB];
    __shared__ __align__(16) __nv_bfloat16 sBs[64 * SB];
    __shared__ float sbm[64], sbs[64];
    __shared__ float warp_red[8];

    int tid = threadIdx.x;
    int warp = tid >> 5, lane = tid & 31;
    int row0 = blockIdx.x * DBM;
    int col0 = blockIdx.y * 64;

    // --- stage A (bf16 g_xh tile, 128 rows x 64 cols = 1024 uint4) ---
    const __nv_bfloat16* gx = g_xh + (size_t)row0 * XD_;
    #pragma unroll
    for (int i = tid; i < DBM * 8; i += 256) {
        int r = i >> 3, c8 = (i & 7) * 8;
        *(uint4*)(sA + r * SA + c8) = *(const uint4*)(gx + r * XD_ + c8);
    }
    // --- stage B (fp32 weights -> bf16, 64 k x 64 cols) ---
    #pragma unroll
    for (int i = tid; i < 64 * 16; i += 256) {
        int k = i >> 4, c4 = (i & 15) * 4;
        float4 vm = *(const float4*)(Wd_mu + k * YD_ + col0 + c4);
        float4 vs = *(const float4*)(Wd_sig + k * YD_ + col0 + c4);
        *(__nv_bfloat162*)(sBm + k * SB + c4)     = __floats2bfloat162_rn(vm.x, vm.y);
        *(__nv_bfloat162*)(sBm + k * SB + c4 + 2) = __floats2bfloat162_rn(vm.z, vm.w);
        *(__nv_bfloat162*)(sBs + k * SB + c4)     = __floats2bfloat162_rn(vs.x, vs.y);
        *(__nv_bfloat162*)(sBs + k * SB + c4 + 2) = __floats2bfloat162_rn(vs.z, vs.w);
    }
    if (tid < 64) {
        sbm[tid] = bd_mu[col0 + tid];
        sbs[tid] = bd_sig[col0 + tid];
    }
    __syncthreads();

    int wm = warp & 3;          // 4 M-warps x 32 rows
    int wn = warp >> 2;         // 2 N-warps x 32 cols
    int mBase = wm * 32;
    int nBase = wn * 32;
    int g = lane >> 2, tg = lane & 3;
    int mi = lane >> 3, ri = lane & 7;

    uint32_t aBase  = (uint32_t)__cvta_generic_to_shared(sA);
    uint32_t bmBase = (uint32_t)__cvta_generic_to_shared(sBm);
    uint32_t bsBase = (uint32_t)__cvta_generic_to_shared(sBs);
    uint32_t aAddr[2];
    #pragma unroll
    for (int mt = 0; mt < 2; mt++)
        aAddr[mt] = aBase +
            (((mBase + mt * 16 + (mi & 1) * 8 + ri) * SA) + (mi >> 1) * 8) * 2;
    uint32_t bmAddr[2], bsAddr[2];
    #pragma unroll
    for (int p = 0; p < 2; p++) {
        uint32_t off = (((mi & 1) * 8 + ri) * SB + nBase + p * 16 + (mi >> 1) * 8) * 2;
        bmAddr[p] = bmBase + off;
        bsAddr[p] = bsBase + off;
    }

    float cm[2][4][4], cs[2][4][4];
    #pragma unroll
    for (int mt = 0; mt < 2; mt++)
        #pragma unroll
        for (int nt = 0; nt < 4; nt++)
            #pragma unroll
            for (int r = 0; r < 4; r++) { cm[mt][nt][r] = 0.f; cs[mt][nt][r] = 0.f; }

    #pragma unroll
    for (int ks = 0; ks < 4; ks++) {
        uint32_t a[2][4];
        ldsm_x4(a[0], aAddr[0] + ks * 32);
        ldsm_x4(a[1], aAddr[1] + ks * 32);
        uint32_t bm[2][4], bs[2][4];
        #pragma unroll
        for (int p = 0; p < 2; p++) {
            ldsm_x4_t(bm[p], bmAddr[p] + ks * (16 * SB * 2));
            ldsm_x4_t(bs[p], bsAddr[p] + ks * (16 * SB * 2));
        }
        #pragma unroll
        for (int nt = 0; nt < 4; nt++) {
            int p = nt >> 1, sel = (nt & 1) * 2;
            #pragma unroll
            for (int mt = 0; mt < 2; mt++) {
                MMA_BF16(cm[mt][nt], a[mt], bm[p][sel], bm[p][sel + 1]);
                MMA_BF16(cs[mt][nt], a[mt], bs[p][sel], bs[p][sel + 1]);
            }
        }
    }

    // --- fused loss1 epilogue (direct-Y, batched log) ---
    float part = 0.0f;
    #pragma unroll
    for (int mt = 0; mt < 2; mt++) {
        #pragma unroll
        for (int half = 0; half < 2; half++) {
            int row = row0 + mBase + mt * 16 + g + half * 8;
            int n = row / S_;
            const float* yrow = Y + (size_t)n * YD_ + col0;
            float prod = 1.0f;
            #pragma unroll
            for (int nt = 0; nt < 4; nt++) {
                #pragma unroll
                for (int p = 0; p < 2; p++) {
                    int r = half * 2 + p;
                    int cl = nBase + nt * 8 + tg * 2 + p;
                    float mu = cm[mt][nt][r] + sbm[cl];
                    float sg = softplus_fast(cs[mt][nt][r] + sbs[cl]) + 1e-3f;
                    float t = __fdividef(yrow[cl] - mu, sg);
                    part -= 0.5f * t * t;
                    prod *= sg;
                }
            }
            part -= __logf(prod);
        }
    }
    #pragma unroll
    for (int o = 16; o > 0; o >>= 1)
        part += __shfl_down_sync(0xffffffffu, part, o);
    if (lane == 0) warp_red[warp] = part;
    __syncthreads();
    if (tid == 0) {
        float tot = 0.0f;
        #pragma unroll
        for (int w = 0; w < 8; w++) tot += warp_red[w];
        atomicAdd(&g_acc[0], (double)tot);
        __threadfence();
        int ticket = atomicAdd(&g_cnt, 1);
        if (ticket == DEC_GRID - 1) {
            g_cnt = 0;   // reset for next graph replay
            double NSd = (double)NS_;
            double L1   = g_acc[0] - 0.5 * (double)YD_ * LOG2PI * NSd;
            double L234 = g_acc[1] + 0.5 * (double)XD_ * LOG2PI * NSd;
            double totl = (L1 + L234) / (double)S_ + g_acc[2];
            out[0] = (float)(-totl);
        }
    }
}

extern "C" void kernel_launch(void* const* d_in, const int* in_sizes, int n_in,
                              void* d_out, int out_size)
{
    const float* Y            = (const float*)d_in[0];
    const float* We_mu        = (const float*)d_in[1];
    const float* be_mu        = (const float*)d_in[2];
    const float* We_sig       = (const float*)d_in[3];
    const float* be_sig       = (const float*)d_in[4];
    const float* Wd_mu        = (const float*)d_in[5];
    const float* bd_mu        = (const float*)d_in[6];
    const float* Wd_sig       = (const float*)d_in[7];
    const float* bd_sig       = (const float*)d_in[8];
    const float* phi_mus      = (const float*)d_in[9];
    const float* phi_sigs     = (const float*)d_in[10];
    const float* phi_logits   = (const float*)d_in[11];
    const float* theta_mus    = (const float*)d_in[12];
    const float* theta_sigs   = (const float*)d_in[13];
    const float* theta_logits = (const float*)d_in[14];
    const float* u_noise      = (const float*)d_in[15];
    const float* eps_noise    = (const float*)d_in[16];
    const float* temperature  = (const float*)d_in[17];

    encoder_kernel<<<N_ / 64, 256>>>(Y, We_mu, be_mu, We_sig, be_sig);
    mixture_kernel<<<N_ / 2, 128>>>(phi_mus, phi_sigs, phi_logits,
                                    theta_mus, theta_sigs, theta_logits,
                                    u_noise, eps_noise, temperature);
    decoder_kernel<<<dim3(NS_ / DBM, YD_ / 64), 256>>>(Y, Wd_mu, bd_mu,
                                                       Wd_sig, bd_sig,
                                                       (float*)d_out);
}

// round 9
// speedup vs baseline: 1.1523x; 1.0251x over previous
#include <cuda_runtime.h>
#include <cuda_bf16.h>
#include <cstdint>

#define N_   8192
#define YD_  512
#define XD_  64
#define K_   16
#define S_   10
#define NS_  (N_*S_)
#define LOG2PI 1.8378770664093453

// ---- scratch (device globals) ----
__device__ float g_enc_mu[N_*XD_];
__device__ float g_enc_sig[N_*XD_];
__device__ __nv_bfloat16 g_xh[NS_*XD_];
__device__ double g_acc[4];   // 0: loss1, 1: loss2+3+4, 2: loss5
__device__ int g_cnt = 0;

__device__ __forceinline__ float softplus_f(float v) {
    return fmaxf(v, 0.0f) + log1pf(__expf(-fabsf(v)));
}
__device__ __forceinline__ float softplus_fast(float v) {
    return fmaxf(v, 0.0f) + __logf(1.0f + __expf(-fabsf(v)));
}
__device__ __forceinline__ void ldsm_x4(uint32_t* r, uint32_t addr) {
    asm volatile("ldmatrix.sync.aligned.m8n8.x4.shared.b16 {%0,%1,%2,%3}, [%4];"
        : "=r"(r[0]), "=r"(r[1]), "=r"(r[2]), "=r"(r[3]) : "r"(addr));
}
__device__ __forceinline__ void ldsm_x4_t(uint32_t* r, uint32_t addr) {
    asm volatile("ldmatrix.sync.aligned.m8n8.x4.trans.shared.b16 {%0,%1,%2,%3}, [%4];"
        : "=r"(r[0]), "=r"(r[1]), "=r"(r[2]), "=r"(r[3]) : "r"(addr));
}
#define MMA_BF16(C, A, B0, B1)                                          \
    asm volatile(                                                       \
        "mma.sync.aligned.m16n8k16.row.col.f32.bf16.bf16.f32 "          \
        "{%0,%1,%2,%3}, {%4,%5,%6,%7}, {%8,%9}, {%0,%1,%2,%3};"         \
        : "+f"(C[0]), "+f"(C[1]), "+f"(C[2]), "+f"(C[3])                \
        : "r"(A[0]), "r"(A[1]), "r"(A[2]), "r"(A[3]), "r"(B0), "r"(B1))

// ============================================================
// Kernel 1: bf16 encoder GEMM, BM=32, register-prefetch double
// buffering, inline fp32->bf16 conversion. grid 256, 8 warps
// (2M x 4N), warp tile 16x32. Zeroes g_acc (block 0).
// A tile: 32r x 64k = 512 float4 (2/thread, >>4 / &15).
// B tile: 64k x 128c = 2048 float4 (8/thread, >>5 / &31).
// ============================================================
#define ESA 72
#define ESB 136

__global__ void __launch_bounds__(256) encoder_kernel(
    const float* __restrict__ Y,
    const float* __restrict__ We_mu, const float* __restrict__ be_mu,
    const float* __restrict__ We_sig, const float* __restrict__ be_sig)
{
    __shared__ __align__(16) __nv_bfloat16 sA[32 * ESA];
    __shared__ __align__(16) __nv_bfloat16 sB[64 * ESB];

    int tid = threadIdx.x;
    int warp = tid >> 5, lane = tid & 31;
    int row0 = blockIdx.x * 32;

    if (blockIdx.x == 0 && tid < 4) g_acc[tid] = 0.0;

    int ar  = tid >> 4, ac4 = (tid & 15) * 4;
    int ar2 = ar + 16;
    float4 rA[2];
    float4 rBf[8];

    #define ENC_LOAD(kc)                                                     \
    {   int k0 = (kc) * 64;                                                  \
        rA[0] = *(const float4*)(Y + (size_t)(row0 + ar) * YD_ + k0 + ac4);  \
        rA[1] = *(const float4*)(Y + (size_t)(row0 + ar2) * YD_ + k0 + ac4); \
        _Pragma("unroll")                                                    \
        for (int j = 0; j < 8; j++) {                                        \
            int i = tid + j * 256;                                           \
            int k = i >> 5, c4 = (i & 31) * 4;                               \
            const float* src = (c4 < 64) ? We_mu + (k0 + k) * XD_ + c4       \
                                         : We_sig + (k0 + k) * XD_ + (c4 - 64); \
            rBf[j] = *(const float4*)src;                                    \
        }                                                                    \
    }
    #define ENC_STORE()                                                     \
    {   *(__nv_bfloat162*)(sA + ar * ESA + ac4)      = __floats2bfloat162_rn(rA[0].x, rA[0].y); \
        *(__nv_bfloat162*)(sA + ar * ESA + ac4 + 2)  = __floats2bfloat162_rn(rA[0].z, rA[0].w); \
        *(__nv_bfloat162*)(sA + ar2 * ESA + ac4)     = __floats2bfloat162_rn(rA[1].x, rA[1].y); \
        *(__nv_bfloat162*)(sA + ar2 * ESA + ac4 + 2) = __floats2bfloat162_rn(rA[1].z, rA[1].w); \
        _Pragma("unroll")                                                    \
        for (int j = 0; j < 8; j++) {                                        \
            int i = tid + j * 256;                                           \
            int k = i >> 5, c4 = (i & 31) * 4;                               \
            *(__nv_bfloat162*)(sB + k * ESB + c4)     = __floats2bfloat162_rn(rBf[j].x, rBf[j].y); \
            *(__nv_bfloat162*)(sB + k * ESB + c4 + 2) = __floats2bfloat162_rn(rBf[j].z, rBf[j].w); \
        }                                                                    \
    }

    int mBase = (warp & 1) * 16;
    int nBase = (warp >> 1) * 32;
    int g = lane >> 2, tg = lane & 3;
    int mi = lane >> 3, ri = lane & 7;

    uint32_t aBase = (uint32_t)__cvta_generic_to_shared(sA);
    uint32_t bBase = (uint32_t)__cvta_generic_to_shared(sB);
    uint32_t aAddr = aBase +
        (((mBase + (mi & 1) * 8 + ri) * ESA) + (mi >> 1) * 8) * 2;
    uint32_t bAddr[2];
    #pragma unroll
    for (int p = 0; p < 2; p++)
        bAddr[p] = bBase +
            ((((mi & 1) * 8 + ri) * ESB) + nBase + p * 16 + (mi >> 1) * 8) * 2;

    float acc[4][4];
    #pragma unroll
    for (int nt = 0; nt < 4; nt++)
        #pragma unroll
        for (int r = 0; r < 4; r++) acc[nt][r] = 0.f;

    ENC_LOAD(0);
    for (int kc = 0; kc < 8; kc++) {
        ENC_STORE();
        __syncthreads();
        if (kc < 7) ENC_LOAD(kc + 1);   // prefetch overlaps MMAs
        #pragma unroll
        for (int ks = 0; ks < 4; ks++) {
            uint32_t a[4];
            ldsm_x4(a, aAddr + ks * 32);
            uint32_t b[2][4];
            ldsm_x4_t(b[0], bAddr[0] + ks * (16 * ESB * 2));
            ldsm_x4_t(b[1], bAddr[1] + ks * (16 * ESB * 2));
            #pragma unroll
            for (int nt = 0; nt < 4; nt++) {
                int p = nt >> 1, sel = (nt & 1) * 2;
                MMA_BF16(acc[nt], a, b[p][sel], b[p][sel + 1]);
            }
        }
        __syncthreads();
    }

    #pragma unroll
    for (int half = 0; half < 2; half++) {
        int row = row0 + mBase + g + half * 8;
        #pragma unroll
        for (int nt = 0; nt < 4; nt++) {
            #pragma unroll
            for (int p = 0; p < 2; p++) {
                int cl = nBase + nt * 8 + tg * 2 + p;
                float c = acc[nt][half * 2 + p];
                if (cl < 64) {
                    g_enc_mu[row * XD_ + cl] = c + be_mu[cl];
                } else {
                    int cc = cl - 64;
                    g_enc_sig[row * XD_ + cc] = softplus_f(c + be_sig[cc]) + 1e-3f;
                }
            }
        }
    }
}

// ============================================================
// Kernel 2: fused GMM responsibilities + gumbel-softmax mixtures
// (R8 exact). Two n per 128-thread block.
// ============================================================
__global__ void __launch_bounds__(128) mixture_kernel(
    const float* __restrict__ phi_mus, const float* __restrict__ phi_sigs,
    const float* __restrict__ phi_logits,
    const float* __restrict__ theta_mus, const float* __restrict__ theta_sigs,
    const float* __restrict__ theta_logits,
    const float* __restrict__ u_noise, const float* __restrict__ eps_noise,
    const float* __restrict__ temperature)
{
    int tid = threadIdx.x;
    int sub = tid >> 6;
    int d = tid & 63;
    int n = blockIdx.x * 2 + sub;

    __shared__ float s_pmu[16 * 65], s_psg[16 * 65];
    __shared__ float s_tmu[16 * 65], s_tsg[16 * 65];
    __shared__ float em[2][64], es[2][64];
    __shared__ float lpi[16], lth[16];
    __shared__ float zl[2][16], zlp[2][16];
    __shared__ float s_z[2][S_][17];
    __shared__ float sdt[2][S_];
    __shared__ float red[2][16][4];
    __shared__ float wred[2][2];
    __shared__ float sl5[2];

    for (int k = sub; k < 16; k += 2) {
        s_pmu[k * 65 + d] = phi_mus[k * XD_ + d];
        s_psg[k * 65 + d] = phi_sigs[k * XD_ + d];
        s_tmu[k * 65 + d] = theta_mus[k * XD_ + d];
        s_tsg[k * 65 + d] = theta_sigs[k * XD_ + d];
    }
    float emd = g_enc_mu[n * XD_ + d];
    float esd = g_enc_sig[n * XD_ + d];
    em[sub][d] = emd; es[sub][d] = esd;
    float iesd = 1.0f / esd;

    if (tid == 0) {
        float m = -1e30f;
        for (int k = 0; k < 16; k++) m = fmaxf(m, phi_logits[k]);
        float sm = 0.0f;
        for (int k = 0; k < 16; k++) sm += __expf(phi_logits[k] - m);
        float lse = m + __logf(sm);
        for (int k = 0; k < 16; k++) lpi[k] = phi_logits[k] - lse;
    }
    if (tid == 1) {
        float m = -1e30f;
        for (int k = 0; k < 16; k++) m = fmaxf(m, theta_logits[k]);
        float sm = 0.0f;
        for (int k = 0; k < 16; k++) sm += __expf(theta_logits[k] - m);
        float lse = m + __logf(sm);
        for (int k = 0; k < 16; k++) lth[k] = theta_logits[k] - lse;
    }
    __syncthreads();

    {
        int k = d >> 2, g4 = d & 3;
        float a = 0.0f, prod = 1.0f;
        #pragma unroll
        for (int i = 0; i < 16; i++) {
            int dd = g4 * 16 + i;
            float std = es[sub][dd] + s_psg[k * 65 + dd];
            float t = __fdividef(em[sub][dd] - s_pmu[k * 65 + dd], std);
            a += 0.5f * t * t;
            prod *= std;
        }
        red[sub][k][g4] = a + __logf(prod);
    }
    __syncthreads();
    if (d < 16)
        zl[sub][d] = lpi[d] - 0.5f * 64.0f * (float)LOG2PI
            - (red[sub][d][0] + red[sub][d][1] + red[sub][d][2] + red[sub][d][3]);
    __syncthreads();
    if (d == 0) {
        float m = -1e30f;
        for (int k = 0; k < 16; k++) m = fmaxf(m, zl[sub][k]);
        float sm = 0.0f;
        for (int k = 0; k < 16; k++) sm += __expf(zl[sub][k] - m);
        float lse = m + __logf(sm);
        for (int k = 0; k < 16; k++) zlp[sub][k] = zl[sub][k] - lse;
        float s2 = 0.0f;
        for (int k = 0; k < 16; k++) s2 += __expf(zlp[sub][k]);
        sl5[sub] = __logf(s2);
    }
    __syncthreads();

    float invT = 1.0f / temperature[0];
    if (d < S_) {
        int s = d;
        const float* urow = u_noise + (size_t)n * (S_ * K_) + s * K_;
        float v[16];
        float m = -1e30f;
        #pragma unroll
        for (int k = 0; k < 16; k++) {
            float gg = -__logf(-__logf(urow[k]));
            v[k] = (zlp[sub][k] + gg) * invT;
            m = fmaxf(m, v[k]);
        }
        float sm = 0.0f;
        #pragma unroll
        for (int k = 0; k < 16; k++) { v[k] = __expf(v[k] - m); sm += v[k]; }
        float inv = 1.0f / sm;
        float dt = 0.0f;
        #pragma unroll
        for (int k = 0; k < 16; k++) {
            float z = v[k] * inv;
            s_z[sub][s][k] = z;
            dt = fmaf(z, lth[k] - zlp[sub][k], dt);
        }
        sdt[sub][s] = dt;
    }
    __syncthreads();

    float ms[S_], ssg[S_], tm[S_], tsg[S_], pm[S_], psg[S_];
    #pragma unroll
    for (int s = 0; s < S_; s++) {
        ms[s] = 0.f; ssg[s] = 0.f; tm[s] = 0.f;
        tsg[s] = 0.f; pm[s] = 0.f; psg[s] = 0.f;
    }
    #pragma unroll
    for (int k = 0; k < 16; k++) {
        float pmu  = s_pmu[k * 65 + d];
        float psig = s_psg[k * 65 + d];
        float tmu  = s_tmu[k * 65 + d];
        float tsig = s_tsg[k * 65 + d];
        float ig = __fdividef(1.0f, psig);
        float st = __fdividef(1.0f, iesd + ig);
        float mut = st * fmaf(ig, pmu, iesd * emd);
        #pragma unroll
        for (int s = 0; s < S_; s++) {
            float z = s_z[sub][s][k];
            ms[s]  = fmaf(z, mut, ms[s]);
            ssg[s] = fmaf(z, st, ssg[s]);
            tm[s]  = fmaf(z, tmu, tm[s]);
            tsg[s] = fmaf(z, tsig, tsg[s]);
            pm[s]  = fmaf(z, pmu, pm[s]);
            psg[s] = fmaf(z, psig, psg[s]);
        }
    }

    float lacc = 0.0f;
    float lp = 1.0f;
    #pragma unroll
    for (int s = 0; s < S_; s++) {
        int row = n * S_ + s;
        float x = fmaf(sqrtf(ssg[s]), eps_noise[(size_t)row * XD_ + d], ms[s]);
        g_xh[(size_t)row * XD_ + d] = __float2bfloat16_rn(x);
        float te = (x - emd) * iesd;
        float rt = __fdividef(1.0f, tsg[s]);
        float rp = __fdividef(1.0f, psg[s]);
        float tt = (x - tm[s]) * rt;
        float tp = (x - pm[s]) * rp;
        lacc += 0.5f * (te * te - tt * tt + tp * tp);
        lp *= psg[s] * rt;
    }
    lacc += __logf(lp) + (float)S_ * __logf(esd);

    #pragma unroll
    for (int o = 16; o > 0; o >>= 1)
        lacc += __shfl_down_sync(0xffffffffu, lacc, o);
    if ((tid & 31) == 0) wred[sub][(tid >> 5) & 1] = lacc;
    __syncthreads();
    if (d == 0) {
        float dts = 0.0f;
        #pragma unroll
        for (int s = 0; s < S_; s++) dts += sdt[sub][s];
        double tot = (double)(wred[sub][0] + wred[sub][1]) + (double)dts;
        atomicAdd(&g_acc[1], tot);
        atomicAdd(&g_acc[2], (double)sl5[sub]);
    }
}

// ============================================================
// Kernel 3: bf16 decoder GEMMs fused with loss1 (R8 exact) +
// fused finalize ticket.
// ============================================================
#define SA 72
#define SB 72
#define DBM 128
#define DEC_GRID ((NS_/DBM)*(YD_/64))

__global__ void __launch_bounds__(256) decoder_kernel(
    const float* __restrict__ Y,
    const float* __restrict__ Wd_mu, const float* __restrict__ bd_mu,
    const float* __restrict__ Wd_sig, const float* __restrict__ bd_sig,
    float* __restrict__ out)
{
    __shared__ __align__(16) __nv_bfloat16 sA[DBM * SA];
    __shared__ __align__(16) __nv_bfloat16 sBm[64 * SB];
    __shared__ __align__(16) __nv_bfloat16 sBs[64 * SB];
    __shared__ float sbm[64], sbs[64];
    __shared__ float warp_red[8];

    int tid = threadIdx.x;
    int warp = tid >> 5, lane = tid & 31;
    int row0 = blockIdx.x * DBM;
    int col0 = blockIdx.y * 64;

    const __nv_bfloat16* gx = g_xh + (size_t)row0 * XD_;
    #pragma unroll
    for (int i = tid; i < DBM * 8; i += 256) {
        int r = i >> 3, c8 = (i & 7) * 8;
        *(uint4*)(sA + r * SA + c8) = *(const uint4*)(gx + r * XD_ + c8);
    }
    #pragma unroll
    for (int i = tid; i < 64 * 16; i += 256) {
        int k = i >> 4, c4 = (i & 15) * 4;
        float4 vm = *(const float4*)(Wd_mu + k * YD_ + col0 + c4);
        float4 vs = *(const float4*)(Wd_sig + k * YD_ + col0 + c4);
        *(__nv_bfloat162*)(sBm + k * SB + c4)     = __floats2bfloat162_rn(vm.x, vm.y);
        *(__nv_bfloat162*)(sBm + k * SB + c4 + 2) = __floats2bfloat162_rn(vm.z, vm.w);
        *(__nv_bfloat162*)(sBs + k * SB + c4)     = __floats2bfloat162_rn(vs.x, vs.y);
        *(__nv_bfloat162*)(sBs + k * SB + c4 + 2) = __floats2bfloat162_rn(vs.z, vs.w);
    }
    if (tid < 64) {
        sbm[tid] = bd_mu[col0 + tid];
        sbs[tid] = bd_sig[col0 + tid];
    }
    __syncthreads();

    int wm = warp & 3;
    int wn = warp >> 2;
    int mBase = wm * 32;
    int nBase = wn * 32;
    int g = lane >> 2, tg = lane & 3;
    int mi = lane >> 3, ri = lane & 7;

    uint32_t aBase  = (uint32_t)__cvta_generic_to_shared(sA);
    uint32_t bmBase = (uint32_t)__cvta_generic_to_shared(sBm);
    uint32_t bsBase = (uint32_t)__cvta_generic_to_shared(sBs);
    uint32_t aAddr[2];
    #pragma unroll
    for (int mt = 0; mt < 2; mt++)
        aAddr[mt] = aBase +
            (((mBase + mt * 16 + (mi & 1) * 8 + ri) * SA) + (mi >> 1) * 8) * 2;
    uint32_t bmAddr[2], bsAddr[2];
    #pragma unroll
    for (int p = 0; p < 2; p++) {
        uint32_t off = (((mi & 1) * 8 + ri) * SB + nBase + p * 16 + (mi >> 1) * 8) * 2;
        bmAddr[p] = bmBase + off;
        bsAddr[p] = bsBase + off;
    }

    float cm[2][4][4], cs[2][4][4];
    #pragma unroll
    for (int mt = 0; mt < 2; mt++)
        #pragma unroll
        for (int nt = 0; nt < 4; nt++)
            #pragma unroll
            for (int r = 0; r < 4; r++) { cm[mt][nt][r] = 0.f; cs[mt][nt][r] = 0.f; }

    #pragma unroll
    for (int ks = 0; ks < 4; ks++) {
        uint32_t a[2][4];
        ldsm_x4(a[0], aAddr[0] + ks * 32);
        ldsm_x4(a[1], aAddr[1] + ks * 32);
        uint32_t bm[2][4], bs[2][4];
        #pragma unroll
        for (int p = 0; p < 2; p++) {
            ldsm_x4_t(bm[p], bmAddr[p] + ks * (16 * SB * 2));
            ldsm_x4_t(bs[p], bsAddr[p] + ks * (16 * SB * 2));
        }
        #pragma unroll
        for (int nt = 0; nt < 4; nt++) {
            int p = nt >> 1, sel = (nt & 1) * 2;
            #pragma unroll
            for (int mt = 0; mt < 2; mt++) {
                MMA_BF16(cm[mt][nt], a[mt], bm[p][sel], bm[p][sel + 1]);
                MMA_BF16(cs[mt][nt], a[mt], bs[p][sel], bs[p][sel + 1]);
            }
        }
    }

    float part = 0.0f;
    #pragma unroll
    for (int mt = 0; mt < 2; mt++) {
        #pragma unroll
        for (int half = 0; half < 2; half++) {
            int row = row0 + mBase + mt * 16 + g + half * 8;
            int n = row / S_;
            const float* yrow = Y + (size_t)n * YD_ + col0;
            float prod = 1.0f;
            #pragma unroll
            for (int nt = 0; nt < 4; nt++) {
                #pragma unroll
                for (int p = 0; p < 2; p++) {
                    int r = half * 2 + p;
                    int cl = nBase + nt * 8 + tg * 2 + p;
                    float mu = cm[mt][nt][r] + sbm[cl];
                    float sg = softplus_fast(cs[mt][nt][r] + sbs[cl]) + 1e-3f;
                    float t = __fdividef(yrow[cl] - mu, sg);
                    part -= 0.5f * t * t;
                    prod *= sg;
                }
            }
            part -= __logf(prod);
        }
    }
    #pragma unroll
    for (int o = 16; o > 0; o >>= 1)
        part += __shfl_down_sync(0xffffffffu, part, o);
    if (lane == 0) warp_red[warp] = part;
    __syncthreads();
    if (tid == 0) {
        float tot = 0.0f;
        #pragma unroll
        for (int w = 0; w < 8; w++) tot += warp_red[w];
        atomicAdd(&g_acc[0], (double)tot);
        __threadfence();
        int ticket = atomicAdd(&g_cnt, 1);
        if (ticket == DEC_GRID - 1) {
            g_cnt = 0;
            double NSd = (double)NS_;
            double L1   = g_acc[0] - 0.5 * (double)YD_ * LOG2PI * NSd;
            double L234 = g_acc[1] + 0.5 * (double)XD_ * LOG2PI * NSd;
            double totl = (L1 + L234) / (double)S_ + g_acc[2];
            out[0] = (float)(-totl);
        }
    }
}

extern "C" void kernel_launch(void* const* d_in, const int* in_sizes, int n_in,
                              void* d_out, int out_size)
{
    const float* Y            = (const float*)d_in[0];
    const float* We_mu        = (const float*)d_in[1];
    const float* be_mu        = (const float*)d_in[2];
    const float* We_sig       = (const float*)d_in[3];
    const float* be_sig       = (const float*)d_in[4];
    const float* Wd_mu        = (const float*)d_in[5];
    const float* bd_mu        = (const float*)d_in[6];
    const float* Wd_sig       = (const float*)d_in[7];
    const float* bd_sig       = (const float*)d_in[8];
    const float* phi_mus      = (const float*)d_in[9];
    const float* phi_sigs     = (const float*)d_in[10];
    const float* phi_logits   = (const float*)d_in[11];
    const float* theta_mus    = (const float*)d_in[12];
    const float* theta_sigs   = (const float*)d_in[13];
    const float* theta_logits = (const float*)d_in[14];
    const float* u_noise      = (const float*)d_in[15];
    const float* eps_noise    = (const float*)d_in[16];
    const float* temperature  = (const float*)d_in[17];

    encoder_kernel<<<N_ / 32, 256>>>(Y, We_mu, be_mu, We_sig, be_sig);
    mixture_kernel<<<N_ / 2, 128>>>(phi_mus, phi_sigs, phi_logits,
                                    theta_mus, theta_sigs, theta_logits,
                                    u_noise, eps_noise, temperature);
    decoder_kernel<<<dim3(NS_ / DBM, YD_ / 64), 256>>>(Y, Wd_mu, bd_mu,
                                                       Wd_sig, bd_sig,
                                                       (float*)d_out);
}